// round 10
// baseline (speedup 1.0000x reference)
#include <cuda_runtime.h>
#include <cuda_bf16.h>
#include <cstdint>

#define BB 4
#define NN 4096
#define FF 32
#define KK 6
#define OO 128

// ---- GEMM tiling ----
#define BM 64                   // rows per CTA (4 warps x 16 rows)
#define KC 64                   // k per chunk
#define NSTAGE 4
#define NCHUNK (NN / KC)        // 64
#define PK (KK * FF)            // 192

// stage layout (bytes): A hi/lo planes 64x80, B hi/lo planes 32x80
#define AROW 80
#define APLANE (BM * AROW)                  // 5120
#define AL_OFF APLANE
#define BROW 80
#define BPLANE (FF * BROW)                  // 2560
#define BH_OFF (2 * APLANE)                 // 10240
#define BL_OFF (BH_OFF + BPLANE)            // 12800
#define STAGE_BYTES (BH_OFF + 2 * BPLANE)   // 15360
#define SMEM_TOTAL (NSTAGE * STAGE_BYTES)   // 61440

#define QMAX 32512.0f
#define L_RANGE 0.125f
#define X_RANGE 8.0f

// ---- scratch ----
__device__ float g_bufA[BB * NN * FF];
__device__ float g_bufB[BB * NN * FF];
__device__ char  g_Lh[(size_t)BB * NN * NN];            // L int16 hi bytes
__device__ char  g_Ll[(size_t)BB * NN * NN];            // L int16 lo bytes
__device__ char  g_bh[2][BB * FF * NN];                 // T planes hi, ping-pong
__device__ char  g_bl[2][BB * FF * NN];                 // T planes lo
__device__ __nv_bfloat16 g_btp_hi[(size_t)BB * NN * PK];
__device__ __nv_bfloat16 g_btp_lo[(size_t)BB * NN * PK];
__device__ __nv_bfloat16 g_wt_hi[OO * PK];
__device__ __nv_bfloat16 g_wt_lo[OO * PK];
__device__ int g_scale_i[8];                            // |T_k| maxes as float bits

__device__ __forceinline__ uint32_t smem_u32(const void* p) {
    uint32_t a;
    asm("{ .reg .u64 t; cvta.to.shared.u64 t, %1; cvt.u32.u64 %0, t; }" : "=r"(a) : "l"(p));
    return a;
}
__device__ __forceinline__ void cp16(uint32_t dst, const void* src) {
    asm volatile("cp.async.cg.shared.global [%0], [%1], 16;" :: "r"(dst), "l"(src));
}
#define CP_COMMIT() asm volatile("cp.async.commit_group;" ::: "memory")
#define CP_WAIT(n)  asm volatile("cp.async.wait_group %0;" :: "n"(n) : "memory")

// bf16 hi/lo split of a float pair (for proj slab export)
__device__ __forceinline__ void split2(float x, float y, uint32_t& hi, uint32_t& lo) {
    asm("cvt.rn.bf16x2.f32 %0, %1, %2;" : "=r"(hi) : "f"(y), "f"(x));
    const float h0 = __uint_as_float(hi << 16);
    const float h1 = __uint_as_float(hi & 0xFFFF0000u);
    const float l0 = x - h0;
    const float l1 = y - h1;
    asm("cvt.rn.bf16x2.f32 %0, %1, %2;" : "=r"(lo) : "f"(l1), "f"(l0));
}

__device__ __forceinline__ void mma16816(float* c,
                                         uint32_t a0, uint32_t a1, uint32_t a2, uint32_t a3,
                                         uint32_t b0, uint32_t b1) {
    asm volatile(
        "mma.sync.aligned.m16n8k16.row.col.f32.bf16.bf16.f32 "
        "{%0,%1,%2,%3}, {%4,%5,%6,%7}, {%8,%9}, {%0,%1,%2,%3};"
        : "+f"(c[0]), "+f"(c[1]), "+f"(c[2]), "+f"(c[3])
        : "r"(a0), "r"(a1), "r"(a2), "r"(a3), "r"(b0), "r"(b1));
}

// s8 IMMA m16n8k32, s32 accumulate
__device__ __forceinline__ void imma(int* c,
                                     uint32_t a0, uint32_t a1, uint32_t a2, uint32_t a3,
                                     uint32_t b0, uint32_t b1) {
    asm volatile(
        "mma.sync.aligned.m16n8k32.row.col.s32.s8.s8.s32 "
        "{%0,%1,%2,%3}, {%4,%5,%6,%7}, {%8,%9}, {%0,%1,%2,%3};"
        : "+r"(c[0]), "+r"(c[1]), "+r"(c[2]), "+r"(c[3])
        : "r"(a0), "r"(a1), "r"(a2), "r"(a3), "r"(b0), "r"(b1));
}

// int16 quant + signed byte split: q = 256*h + l, h,l in [-127,127]/[-128,127]
__device__ __forceinline__ void quant16(float v, float inv, int& h, int& l) {
    float q = rintf(v * inv);
    q = fminf(fmaxf(q, -QMAX), QMAX);
    const int qi = (int)q;
    h = (qi + 128) >> 8;
    l = qi - (h << 8);
}

// ---------------------------------------------------------------------------
// prep_L: L fp32 -> int8 hi/lo planes (one-time), fully coalesced
// ---------------------------------------------------------------------------
__global__ __launch_bounds__(256) void prep_L_k(const float* __restrict__ L) {
    const size_t i4 = (size_t)blockIdx.x * 256 + threadIdx.x;   // float4 index
    const float4 v = ((const float4*)L)[i4];
    const float inv = QMAX / L_RANGE;
    int h0, l0, h1, l1, h2, l2, h3, l3;
    quant16(v.x, inv, h0, l0);
    quant16(v.y, inv, h1, l1);
    quant16(v.z, inv, h2, l2);
    quant16(v.w, inv, h3, l3);
    const uint32_t hp = (h0 & 0xFF) | ((h1 & 0xFF) << 8) | ((h2 & 0xFF) << 16) | ((h3 & 0xFF) << 24);
    const uint32_t lp = (l0 & 0xFF) | ((l1 & 0xFF) << 8) | ((l2 & 0xFF) << 16) | ((l3 & 0xFF) << 24);
    ((uint32_t*)g_Lh)[i4] = hp;
    ((uint32_t*)g_Ll)[i4] = lp;
}

// ---------------------------------------------------------------------------
// prep_x: x -> int8 planes buf0 (static scale) + bf16 proj slab slot 0 + scale[0]
// ---------------------------------------------------------------------------
__global__ __launch_bounds__(256) void prep_x_k(const float* __restrict__ T) {
    const int idx = blockIdx.x * 256 + threadIdx.x;     // [b][f][n] flat
    const int n = idx & (NN - 1);
    const int f = (idx >> 12) & (FF - 1);
    const int b = idx >> 17;
    const float a = T[((size_t)b * NN + n) * FF + f];
    int h, l;
    quant16(a, QMAX / X_RANGE, h, l);
    g_bh[0][idx] = (char)h;
    g_bl[0][idx] = (char)l;
    // bf16 slab slot 0
    const __nv_bfloat16 bh = __float2bfloat16_rn(a);
    const __nv_bfloat16 bl = __float2bfloat16_rn(a - __bfloat162float(bh));
    const size_t pidx = ((size_t)b * NN + n) * PK + f;
    g_btp_hi[pidx] = bh;
    g_btp_lo[pidx] = bl;
    if (idx == 0) g_scale_i[0] = __float_as_int(X_RANGE);
}

// ---------------------------------------------------------------------------
// prep_T: T_k fp32 -> int8 planes (dynamic scale from g_scale_i[slot])
// ---------------------------------------------------------------------------
__global__ __launch_bounds__(256) void prep_T_k(const float* __restrict__ T, int slot, int pp) {
    const int idx = blockIdx.x * 256 + threadIdx.x;
    const int n = idx & (NN - 1);
    const int f = (idx >> 12) & (FF - 1);
    const int b = idx >> 17;
    const float a = T[((size_t)b * NN + n) * FF + f];
    const float smax = __int_as_float(g_scale_i[slot]);
    int h, l;
    quant16(a, QMAX / smax, h, l);
    g_bh[pp][idx] = (char)h;
    g_bl[pp][idx] = (char)l;
}

// ---------------------------------------------------------------------------
// prep_w: Wt[o][k6*32+f] = theta[k6] * W[k6][f][o], bf16 hi/lo
// ---------------------------------------------------------------------------
__global__ __launch_bounds__(256) void prep_w(
    const float* __restrict__ W, const float* __restrict__ theta)
{
    const int idx = blockIdx.x * 256 + threadIdx.x;
    const int o  = idx & (OO - 1);
    const int kf = idx >> 7;
    const int k6 = kf >> 5;
    const float v = theta[k6] * W[(size_t)kf * OO + o];
    const __nv_bfloat16 h = __float2bfloat16_rn(v);
    const size_t w = (size_t)o * PK + kf;
    g_wt_hi[w] = h;
    g_wt_lo[w] = __float2bfloat16_rn(v - __bfloat162float(h));
}

// ---------------------------------------------------------------------------
// IMMA GEMM: Tnew = alpha * (sA*sB * Lq @ Tq) + beta * Tpp
// exact int16 x int16 via 4 s8 products; R4 pipeline discipline.
// ---------------------------------------------------------------------------
__global__ __launch_bounds__(128, 3) void cheb_imma(
    const char* __restrict__ Bhp,
    const char* __restrict__ Blp,
    const float* __restrict__ Tpp,
    float* __restrict__ Tnew,
    float alpha, float beta,
    int sBslot, int maxSlot, int pslot)
{
    extern __shared__ __align__(16) char smem[];
    const uint32_t sb = smem_u32(smem);

    const int tid  = threadIdx.x;
    const int lane = tid & 31;
    const int wl   = tid >> 5;
    const int b    = blockIdx.y;
    const int row0 = blockIdx.x * BM;

    const char* Ah = g_Lh + ((size_t)b * NN + row0) * NN;
    const char* Al = g_Ll + ((size_t)b * NN + row0) * NN;
    const char* Bh = Bhp + (size_t)b * FF * NN;
    const char* Bl = Blp + (size_t)b * FF * NN;

    auto issue = [&](int c) {
        const uint32_t st = sb + (uint32_t)(c & (NSTAGE - 1)) * STAGE_BYTES;
        const int k0 = c * KC;
        // A planes: 2 x 64 rows x 4 cp16 = 512 -> 4/thread
#pragma unroll
        for (int i = 0; i < 4; i++) {
            const int idx = i * 128 + tid;
            const int pl = idx >> 8;
            const int r = (idx >> 2) & 63, g = idx & 3;
            const char* src = (pl ? Al : Ah) + (size_t)r * NN + k0 + g * 16;
            cp16(st + pl * APLANE + r * AROW + g * 16, src);
        }
        // B planes: 2 x 32 f x 4 cp16 = 256 -> 2/thread
#pragma unroll
        for (int i = 0; i < 2; i++) {
            const int idx = i * 128 + tid;
            const int pl = idx >> 7;
            const int f = (idx >> 2) & 31, g = idx & 3;
            const char* src = (pl ? Bl : Bh) + (size_t)f * NN + k0 + g * 16;
            cp16(st + BH_OFF + pl * BPLANE + f * BROW + g * 16, src);
        }
    };

#pragma unroll
    for (int s = 0; s < NSTAGE - 1; s++) { issue(s); CP_COMMIT(); }

    int acc_hh[4][4], acc_mid[4][4], acc_ll[4][4];
#pragma unroll
    for (int i = 0; i < 4; i++)
#pragma unroll
        for (int j = 0; j < 4; j++) { acc_hh[i][j] = 0; acc_mid[i][j] = 0; acc_ll[i][j] = 0; }

    const int rsub = lane >> 2;
    const int q    = lane & 3;

    for (int c = 0; c < NCHUNK; c++) {
        CP_WAIT(NSTAGE - 2);
        __syncthreads();
        if (c + NSTAGE - 1 < NCHUNK) issue(c + NSTAGE - 1);
        CP_COMMIT();

        const char* st = smem + (c & (NSTAGE - 1)) * STAGE_BYTES;
        const int arow = wl * 16 + rsub;

#pragma unroll
        for (int ks = 0; ks < 2; ks++) {
            const char* ap = st + arow * AROW + ks * 32 + q * 4;
            const uint32_t ha0 = *(const uint32_t*)(ap);
            const uint32_t ha1 = *(const uint32_t*)(ap + 8 * AROW);
            const uint32_t ha2 = *(const uint32_t*)(ap + 16);
            const uint32_t ha3 = *(const uint32_t*)(ap + 8 * AROW + 16);
            const uint32_t la0 = *(const uint32_t*)(ap + APLANE);
            const uint32_t la1 = *(const uint32_t*)(ap + APLANE + 8 * AROW);
            const uint32_t la2 = *(const uint32_t*)(ap + APLANE + 16);
            const uint32_t la3 = *(const uint32_t*)(ap + APLANE + 8 * AROW + 16);

#pragma unroll
            for (int nb = 0; nb < 4; nb++) {
                const char* bp = st + BH_OFF + (nb * 8 + rsub) * BROW + ks * 32 + q * 4;
                const uint32_t hb0 = *(const uint32_t*)(bp);
                const uint32_t hb1 = *(const uint32_t*)(bp + 16);
                const uint32_t lb0 = *(const uint32_t*)(bp + BPLANE);
                const uint32_t lb1 = *(const uint32_t*)(bp + BPLANE + 16);

                imma(acc_hh[nb],  ha0, ha1, ha2, ha3, hb0, hb1);
                imma(acc_mid[nb], ha0, ha1, ha2, ha3, lb0, lb1);
                imma(acc_mid[nb], la0, la1, la2, la3, hb0, hb1);
                imma(acc_ll[nb],  la0, la1, la2, la3, lb0, lb1);
            }
        }
    }

    // ---- epilogue: dequant + beta + exports + max|T| ----
    const float sA = L_RANGE / QMAX;
    const float sB = __int_as_float(g_scale_i[sBslot]) / QMAX;
    const float s  = alpha * sA * sB;

    const int kq = q * 2;
    const int rA = row0 + wl * 16 + rsub;
    float mymax = 0.0f;

#pragma unroll
    for (int nb = 0; nb < 4; nb++) {
        const int col = nb * 8 + kq;
        const size_t o0 = ((size_t)b * NN + rA) * FF + col;
        const size_t o1 = o0 + 8 * FF;
        float2 v0, v1;
        v0.x = s * (65536.0f * (float)acc_hh[nb][0] + 256.0f * (float)acc_mid[nb][0] + (float)acc_ll[nb][0]);
        v0.y = s * (65536.0f * (float)acc_hh[nb][1] + 256.0f * (float)acc_mid[nb][1] + (float)acc_ll[nb][1]);
        v1.x = s * (65536.0f * (float)acc_hh[nb][2] + 256.0f * (float)acc_mid[nb][2] + (float)acc_ll[nb][2]);
        v1.y = s * (65536.0f * (float)acc_hh[nb][3] + 256.0f * (float)acc_mid[nb][3] + (float)acc_ll[nb][3]);
        if (beta != 0.0f) {
            const float2 q0 = *(const float2*)(Tpp + o0);
            const float2 q1 = *(const float2*)(Tpp + o1);
            v0.x += beta * q0.x; v0.y += beta * q0.y;
            v1.x += beta * q1.x; v1.y += beta * q1.y;
        }
        *(float2*)(Tnew + o0) = v0;
        *(float2*)(Tnew + o1) = v1;

        mymax = fmaxf(mymax, fmaxf(fmaxf(fabsf(v0.x), fabsf(v0.y)), fmaxf(fabsf(v1.x), fabsf(v1.y))));

        // bf16 proj slab export
        uint32_t h0, l0, h1, l1;
        split2(v0.x, v0.y, h0, l0);
        split2(v1.x, v1.y, h1, l1);
        const size_t p0 = ((size_t)b * NN + rA) * PK + pslot * FF + col;
        const size_t p1 = p0 + 8 * PK;
        *(uint32_t*)(g_btp_hi + p0) = h0;
        *(uint32_t*)(g_btp_lo + p0) = l0;
        *(uint32_t*)(g_btp_hi + p1) = h1;
        *(uint32_t*)(g_btp_lo + p1) = l1;
    }

    // warp-reduce max, lane 0 atomicMax (float-as-int valid for >=0)
#pragma unroll
    for (int off = 16; off > 0; off >>= 1)
        mymax = fmaxf(mymax, __shfl_xor_sync(0xFFFFFFFFu, mymax, off));
    if (lane == 0) atomicMax(&g_scale_i[maxSlot], __float_as_int(mymax));
}

// ---------------------------------------------------------------------------
// Fused projection: out[16384,128] = A[16384,192] @ W'[192,128]  (bf16 3-prod)
// ---------------------------------------------------------------------------
#define PJ_STRIDE 100
#define PJ_SMEM (4 * 64 * PJ_STRIDE * 4)

__global__ __launch_bounds__(256, 2) void proj_mma(float* __restrict__ out)
{
    extern __shared__ __align__(16) char smem[];
    uint32_t* Ah = (uint32_t*)smem;
    uint32_t* Al = Ah + 64 * PJ_STRIDE;
    uint32_t* Bh = Al + 64 * PJ_STRIDE;
    uint32_t* Bl = Bh + 64 * PJ_STRIDE;
    const uint32_t sAh = smem_u32(Ah), sAl = smem_u32(Al);
    const uint32_t sBh = smem_u32(Bh), sBl = smem_u32(Bl);

    const int tid = threadIdx.x;
    const int r0 = blockIdx.x * 64;
    const int oh = blockIdx.y;

#pragma unroll
    for (int i = 0; i < 6; i++) {
        const int idx = i * 256 + tid;
        const int row = idx / 24;
        const int ch  = idx % 24;
        cp16(sAh + row * 400 + ch * 16, g_btp_hi + (size_t)(r0 + row) * PK + ch * 8);
        cp16(sAl + row * 400 + ch * 16, g_btp_lo + (size_t)(r0 + row) * PK + ch * 8);
        cp16(sBh + row * 400 + ch * 16, g_wt_hi + (size_t)(oh * 64 + row) * PK + ch * 8);
        cp16(sBl + row * 400 + ch * 16, g_wt_lo + (size_t)(oh * 64 + row) * PK + ch * 8);
    }
    CP_COMMIT();
    CP_WAIT(0);
    __syncthreads();

    const int lane = tid & 31;
    const int wid  = tid >> 5;
    const int mw   = wid & 3;
    const int ow   = wid >> 2;
    const int rsub = lane >> 2;
    const int q    = lane & 3;

    float acc[4][4];
#pragma unroll
    for (int i = 0; i < 4; i++)
#pragma unroll
        for (int j = 0; j < 4; j++) acc[i][j] = 0.0f;

#pragma unroll
    for (int ki = 0; ki < 12; ki++) {
        const int kb2 = ki * 8;
        const uint32_t* Ar = Ah + (mw * 16 + rsub) * PJ_STRIDE + kb2 + q;
        const uint32_t* Alr = Al + (mw * 16 + rsub) * PJ_STRIDE + kb2 + q;
        const uint32_t ah0 = Ar[0],  ah1 = Ar[8 * PJ_STRIDE],  ah2 = Ar[4],  ah3 = Ar[8 * PJ_STRIDE + 4];
        const uint32_t al0 = Alr[0], al1 = Alr[8 * PJ_STRIDE], al2 = Alr[4], al3 = Alr[8 * PJ_STRIDE + 4];

#pragma unroll
        for (int nb = 0; nb < 4; nb++) {
            const int ob = ow * 32 + nb * 8 + rsub;
            const uint32_t* Br = Bh + ob * PJ_STRIDE + kb2 + q;
            const uint32_t* Blr = Bl + ob * PJ_STRIDE + kb2 + q;
            const uint32_t bh0 = Br[0], bh1 = Br[4];
            const uint32_t bl0 = Blr[0], bl1 = Blr[4];

            mma16816(acc[nb], ah0, ah1, ah2, ah3, bh0, bh1);
            mma16816(acc[nb], ah0, ah1, ah2, ah3, bl0, bl1);
            mma16816(acc[nb], al0, al1, al2, al3, bh0, bh1);
        }
    }

    const int row = r0 + mw * 16 + rsub;
#pragma unroll
    for (int nb = 0; nb < 4; nb++) {
        const int col = oh * 64 + ow * 32 + nb * 8 + q * 2;
        *(float2*)(out + (size_t)row * OO + col)       = make_float2(acc[nb][0], acc[nb][1]);
        *(float2*)(out + (size_t)(row + 8) * OO + col) = make_float2(acc[nb][2], acc[nb][3]);
    }
}

// ---------------------------------------------------------------------------
// Launcher
// ---------------------------------------------------------------------------
extern "C" void kernel_launch(void* const* d_in, const int* in_sizes, int n_in,
                              void* d_out, int out_size)
{
    const float* x = nullptr;
    const float* Lm = nullptr;
    const float* W = nullptr;
    const float* theta = nullptr;
    for (int i = 0; i < n_in; i++) {
        switch (in_sizes[i]) {
            case BB * NN * FF: x = (const float*)d_in[i]; break;
            case BB * NN * NN: Lm = (const float*)d_in[i]; break;
            case KK * FF * OO: W = (const float*)d_in[i]; break;
            case KK:           theta = (const float*)d_in[i]; break;
            default: break;
        }
    }
    float* out = (float*)d_out;

    float *bufA = nullptr, *bufB = nullptr;
    char *bh0 = nullptr, *bl0 = nullptr;
    cudaGetSymbolAddress((void**)&bufA, g_bufA);
    cudaGetSymbolAddress((void**)&bufB, g_bufB);
    cudaGetSymbolAddress((void**)&bh0, g_bh);
    cudaGetSymbolAddress((void**)&bl0, g_bl);
    char* bh[2] = { bh0, bh0 + (size_t)BB * FF * NN };
    char* bl[2] = { bl0, bl0 + (size_t)BB * FF * NN };

    cudaFuncSetAttribute(cheb_imma, cudaFuncAttributeMaxDynamicSharedMemorySize, SMEM_TOTAL);
    cudaFuncSetAttribute(proj_mma, cudaFuncAttributeMaxDynamicSharedMemorySize, PJ_SMEM);

    const dim3 gGrid(NN / BM, BB);
    const dim3 xGrid((BB * FF * NN) / 256);
    const dim3 wGrid((PK * OO) / 256);
    const dim3 lGrid((size_t)BB * NN * NN / 4 / 256);
    const dim3 pjGrid((BB * NN) / 64, 2);

    prep_w<<<wGrid, 256>>>(W, theta);
    prep_x_k<<<xGrid, 256>>>(x);
    prep_L_k<<<lGrid, 256>>>(Lm);

    // T1 = L @ x        (B = x planes buf0, scale slot 0; write max -> slot 1)
    cheb_imma<<<gGrid, 128, SMEM_TOTAL>>>(bh[0], bl[0], x, bufA, 1.0f, 0.0f, 0, 1, 1);
    prep_T_k<<<xGrid, 256>>>(bufA, 1, 1);

    // T2 = 2 L @ T1 - x
    cheb_imma<<<gGrid, 128, SMEM_TOTAL>>>(bh[1], bl[1], x, bufB, 2.0f, -1.0f, 1, 2, 2);
    prep_T_k<<<xGrid, 256>>>(bufB, 2, 0);

    // T3 = 2 L @ T2 - T1  (in-place bufA)
    cheb_imma<<<gGrid, 128, SMEM_TOTAL>>>(bh[0], bl[0], bufA, bufA, 2.0f, -1.0f, 2, 3, 3);
    prep_T_k<<<xGrid, 256>>>(bufA, 3, 1);

    // T4 = 2 L @ T3 - T2  (in-place bufB)
    cheb_imma<<<gGrid, 128, SMEM_TOTAL>>>(bh[1], bl[1], bufB, bufB, 2.0f, -1.0f, 3, 4, 4);
    prep_T_k<<<xGrid, 256>>>(bufB, 4, 0);

    // T5 = 2 L @ T4 - T3  (in-place bufA)
    cheb_imma<<<gGrid, 128, SMEM_TOTAL>>>(bh[0], bl[0], bufA, bufA, 2.0f, -1.0f, 4, 5, 5);

    // out = sum_k theta_k T_k W_k
    proj_mma<<<pjGrid, 256, PJ_SMEM>>>(out);
}

// round 11
// speedup vs baseline: 3.7626x; 3.7626x over previous
#include <cuda_runtime.h>
#include <cuda_bf16.h>
#include <cstdint>

#define BB 4
#define NN 4096
#define FF 32
#define KK 6
#define OO 128

// ---- GEMM tiling ----
#define BM 32                   // rows per CTA (2 warps x 16 rows)
#define KC 32                   // k per chunk
#define NSTAGE 4
#define NCHUNK (NN / KC)        // 128
#define GT 64                   // threads per CTA
#define PK (KK * FF)            // 192

#define AROWF 40                                // A smem row stride in floats
#define AROWB (AROWF * 4)                       // 160
#define A_BYTES (BM * AROWB)                    // 5120
#define BROWB 80                                // B smem row stride bytes
#define B_BYTES (FF * BROWB)                    // 2560
#define BHI_OFF A_BYTES
#define BLO_OFF (A_BYTES + B_BYTES)
#define STAGE_BYTES (A_BYTES + 2 * B_BYTES)     // 10240
#define SMEM_TOTAL (NSTAGE * STAGE_BYTES)       // 40960

// ---- scratch ----
__device__ float g_bufA[BB * NN * FF];
__device__ float g_bufB[BB * NN * FF];
__device__ __nv_bfloat16 g_btg_hi[2][BB * FF * NN];
__device__ __nv_bfloat16 g_btg_lo[2][BB * FF * NN];
__device__ __nv_bfloat16 g_btp_hi[(size_t)BB * NN * PK];
__device__ __nv_bfloat16 g_btp_lo[(size_t)BB * NN * PK];
__device__ __nv_bfloat16 g_wt_hi[OO * PK];
__device__ __nv_bfloat16 g_wt_lo[OO * PK];

__device__ __forceinline__ uint32_t smem_u32(const void* p) {
    uint32_t a;
    asm("{ .reg .u64 t; cvta.to.shared.u64 t, %1; cvt.u32.u64 %0, t; }" : "=r"(a) : "l"(p));
    return a;
}
__device__ __forceinline__ void cp16(uint32_t dst, const void* src) {
    asm volatile("cp.async.cg.shared.global [%0], [%1], 16;" :: "r"(dst), "l"(src));
}
#define CP_COMMIT() asm volatile("cp.async.commit_group;" ::: "memory")
#define CP_WAIT(n)  asm volatile("cp.async.wait_group %0;" :: "n"(n) : "memory")

__device__ __forceinline__ void split2(float x, float y, uint32_t& hi, uint32_t& lo) {
    asm("cvt.rn.bf16x2.f32 %0, %1, %2;" : "=r"(hi) : "f"(y), "f"(x));
    const float h0 = __uint_as_float(hi << 16);
    const float h1 = __uint_as_float(hi & 0xFFFF0000u);
    const float l0 = x - h0;
    const float l1 = y - h1;
    asm("cvt.rn.bf16x2.f32 %0, %1, %2;" : "=r"(lo) : "f"(l1), "f"(l0));
}

__device__ __forceinline__ void mma16816(float* c,
                                         uint32_t a0, uint32_t a1, uint32_t a2, uint32_t a3,
                                         uint32_t b0, uint32_t b1) {
    asm volatile(
        "mma.sync.aligned.m16n8k16.row.col.f32.bf16.bf16.f32 "
        "{%0,%1,%2,%3}, {%4,%5,%6,%7}, {%8,%9}, {%0,%1,%2,%3};"
        : "+f"(c[0]), "+f"(c[1]), "+f"(c[2]), "+f"(c[3])
        : "r"(a0), "r"(a1), "r"(a2), "r"(a3), "r"(b0), "r"(b1));
}

// ---------------------------------------------------------------------------
// Prep x: fp32 [b][n][f] -> btg ([b][f][n] hi/lo)  +  btp slot 0
// ---------------------------------------------------------------------------
__global__ __launch_bounds__(256) void prep_b(
    const float* __restrict__ T,
    __nv_bfloat16* __restrict__ gHi,
    __nv_bfloat16* __restrict__ gLo,
    __nv_bfloat16* __restrict__ pHi,
    __nv_bfloat16* __restrict__ pLo)
{
    const int idx = blockIdx.x * 256 + threadIdx.x;
    const int n = idx & (NN - 1);
    const int f = (idx >> 12) & (FF - 1);
    const int b = idx >> 17;
    const float a = T[((size_t)b * NN + n) * FF + f];
    const __nv_bfloat16 h = __float2bfloat16_rn(a);
    const __nv_bfloat16 l = __float2bfloat16_rn(a - __bfloat162float(h));
    gHi[idx] = h;
    gLo[idx] = l;
    const size_t pidx = ((size_t)b * NN + n) * PK + f;
    pHi[pidx] = h;
    pLo[pidx] = l;
}

// ---------------------------------------------------------------------------
// Prep W': Wt[o][k6*32+f] = theta[k6] * W[k6][f][o], bf16 hi/lo
// ---------------------------------------------------------------------------
__global__ __launch_bounds__(256) void prep_w(
    const float* __restrict__ W,
    const float* __restrict__ theta,
    __nv_bfloat16* __restrict__ wHi,
    __nv_bfloat16* __restrict__ wLo)
{
    const int idx = blockIdx.x * 256 + threadIdx.x;
    const int o  = idx & (OO - 1);
    const int kf = idx >> 7;
    const int k6 = kf >> 5;
    const float v = theta[k6] * W[(size_t)kf * OO + o];
    const __nv_bfloat16 h = __float2bfloat16_rn(v);
    const size_t w = (size_t)o * PK + kf;
    wHi[w] = h;
    wLo[w] = __float2bfloat16_rn(v - __bfloat162float(h));
}

// ---------------------------------------------------------------------------
// HMMA GEMM (BM=32, 64 threads, 512 CTAs): R4 pipeline discipline rescaled.
// Tnew = alpha * L @ Tprev + beta * Tpp, plus bf16 term export.
// ---------------------------------------------------------------------------
__global__ __launch_bounds__(GT, 5) void cheb_gemm_tc(
    const float* __restrict__ Lmat,
    const __nv_bfloat16* __restrict__ BtHi,
    const __nv_bfloat16* __restrict__ BtLo,
    const float* __restrict__ Tpp,
    float* __restrict__ Tnew,
    float alpha, float beta,
    __nv_bfloat16* __restrict__ outGHi,
    __nv_bfloat16* __restrict__ outGLo,
    __nv_bfloat16* __restrict__ outPHi,
    __nv_bfloat16* __restrict__ outPLo,
    int pslot)
{
    extern __shared__ __align__(16) char smem[];
    const uint32_t sb = smem_u32(smem);

    const int tid  = threadIdx.x;
    const int lane = tid & 31;
    const int wl   = tid >> 5;       // warp 0..1, owns rows wl*16..+15
    const int b    = blockIdx.y;
    const int row0 = blockIdx.x * BM;

    const float* Lb = Lmat + ((size_t)b * NN + row0) * NN;
    const __nv_bfloat16* bhsrc = BtHi + (size_t)b * FF * NN;
    const __nv_bfloat16* blsrc = BtLo + (size_t)b * FF * NN;

    auto issue = [&](int c) {
        const uint32_t st = sb + (uint32_t)(c % NSTAGE) * STAGE_BYTES;
        const int k0 = c * KC;
        // A: 32 rows x 128B = 256 x 16B chunks, 4 per thread
#pragma unroll
        for (int i = 0; i < 4; i++) {
            const int idx = i * GT + tid;
            const int r = idx >> 3, g = idx & 7;
            cp16(st + r * AROWB + g * 16, Lb + (size_t)r * NN + k0 + g * 4);
        }
        // B: hi+lo, 32 f-rows x 64B each = 256 x 16B, 4 per thread
#pragma unroll
        for (int i = 0; i < 4; i++) {
            const int idx = i * GT + tid;
            const int sel = idx >> 7;
            const int f = (idx >> 2) & 31, g = idx & 3;
            const __nv_bfloat16* src = sel ? blsrc : bhsrc;
            cp16(st + (sel ? BLO_OFF : BHI_OFF) + f * BROWB + g * 16,
                 src + (size_t)f * NN + k0 + g * 8);
        }
    };

#pragma unroll
    for (int s = 0; s < NSTAGE - 1; s++) { issue(s); CP_COMMIT(); }

    float acc[4][4];
#pragma unroll
    for (int i = 0; i < 4; i++)
#pragma unroll
        for (int j = 0; j < 4; j++) acc[i][j] = 0.0f;

    const int rsub = (lane >> 2);
    const int kq   = (lane & 3) * 2;

    for (int i = 0; i < NCHUNK; i++) {
        CP_WAIT(NSTAGE - 2);
        __syncthreads();
        if (i + NSTAGE - 1 < NCHUNK) issue(i + NSTAGE - 1);
        CP_COMMIT();

        const char* st = smem + (i % NSTAGE) * STAGE_BYTES;
        const float* As = (const float*)st;

#pragma unroll
        for (int kf = 0; kf < 2; kf++) {
            const int kb = kf * 16;
            const float* Ap = As + (wl * 16 + rsub) * AROWF + kb + kq;
            const float2 p0 = *(const float2*)(Ap);
            const float2 p1 = *(const float2*)(Ap + 8 * AROWF);
            const float2 p2 = *(const float2*)(Ap + 8);
            const float2 p3 = *(const float2*)(Ap + 8 * AROWF + 8);

            uint32_t ah0, ah1, ah2, ah3, al0, al1, al2, al3;
            split2(p0.x, p0.y, ah0, al0);
            split2(p1.x, p1.y, ah1, al1);
            split2(p2.x, p2.y, ah2, al2);
            split2(p3.x, p3.y, ah3, al3);

#pragma unroll
            for (int nb = 0; nb < 4; nb++) {
                const int n = nb * 8 + rsub;
                const char* bp = st + BHI_OFF + n * BROWB + (kb + kq) * 2;
                const uint32_t bh0 = *(const uint32_t*)(bp);
                const uint32_t bh1 = *(const uint32_t*)(bp + 16);
                const uint32_t bl0 = *(const uint32_t*)(bp + (BLO_OFF - BHI_OFF));
                const uint32_t bl1 = *(const uint32_t*)(bp + (BLO_OFF - BHI_OFF) + 16);

                mma16816(acc[nb], ah0, ah1, ah2, ah3, bh0, bh1);
                mma16816(acc[nb], ah0, ah1, ah2, ah3, bl0, bl1);
                mma16816(acc[nb], al0, al1, al2, al3, bh0, bh1);
            }
        }
    }

    // ---- epilogue: Tnew fp32 + btg [f][n] hi/lo + btp slab slot ----
    const int rA = row0 + wl * 16 + rsub;
#pragma unroll
    for (int nb = 0; nb < 4; nb++) {
        const int col = nb * 8 + kq;
        const size_t o0 = ((size_t)b * NN + rA) * FF + col;
        const size_t o1 = o0 + 8 * FF;
        float2 v0 = make_float2(alpha * acc[nb][0], alpha * acc[nb][1]);
        float2 v1 = make_float2(alpha * acc[nb][2], alpha * acc[nb][3]);
        if (beta != 0.0f) {
            const float2 q0 = *(const float2*)(Tpp + o0);
            const float2 q1 = *(const float2*)(Tpp + o1);
            v0.x += beta * q0.x; v0.y += beta * q0.y;
            v1.x += beta * q1.x; v1.y += beta * q1.y;
        }
        *(float2*)(Tnew + o0) = v0;
        *(float2*)(Tnew + o1) = v1;

        uint32_t h0, l0, h1, l1;
        split2(v0.x, v0.y, h0, l0);
        split2(v1.x, v1.y, h1, l1);

        const size_t p0 = ((size_t)b * NN + rA) * PK + pslot * FF + col;
        const size_t p1 = p0 + 8 * PK;
        *(uint32_t*)(outPHi + p0) = h0;
        *(uint32_t*)(outPLo + p0) = l0;
        *(uint32_t*)(outPHi + p1) = h1;
        *(uint32_t*)(outPLo + p1) = l1;

        const size_t gA = ((size_t)b * FF + col) * NN;
        ((uint16_t*)outGHi)[gA + rA]           = (uint16_t)(h0 & 0xFFFF);
        ((uint16_t*)outGHi)[gA + NN + rA]      = (uint16_t)(h0 >> 16);
        ((uint16_t*)outGLo)[gA + rA]           = (uint16_t)(l0 & 0xFFFF);
        ((uint16_t*)outGLo)[gA + NN + rA]      = (uint16_t)(l0 >> 16);
        ((uint16_t*)outGHi)[gA + rA + 8]       = (uint16_t)(h1 & 0xFFFF);
        ((uint16_t*)outGHi)[gA + NN + rA + 8]  = (uint16_t)(h1 >> 16);
        ((uint16_t*)outGLo)[gA + rA + 8]       = (uint16_t)(l1 & 0xFFFF);
        ((uint16_t*)outGLo)[gA + NN + rA + 8]  = (uint16_t)(l1 >> 16);
    }
}

// ---------------------------------------------------------------------------
// Fused projection: out[16384,128] = A[16384,192] @ W'[192,128]
// ---------------------------------------------------------------------------
#define PJ_STRIDE 100
#define PJ_SMEM (4 * 64 * PJ_STRIDE * 4)

__global__ __launch_bounds__(256, 2) void proj_mma(
    const __nv_bfloat16* __restrict__ pHi,
    const __nv_bfloat16* __restrict__ pLo,
    const __nv_bfloat16* __restrict__ wHi,
    const __nv_bfloat16* __restrict__ wLo,
    float* __restrict__ out)
{
    extern __shared__ __align__(16) char smem[];
    uint32_t* Ah = (uint32_t*)smem;
    uint32_t* Al = Ah + 64 * PJ_STRIDE;
    uint32_t* Bh = Al + 64 * PJ_STRIDE;
    uint32_t* Bl = Bh + 64 * PJ_STRIDE;
    const uint32_t sAh = smem_u32(Ah), sAl = smem_u32(Al);
    const uint32_t sBh = smem_u32(Bh), sBl = smem_u32(Bl);

    const int tid = threadIdx.x;
    const int r0 = blockIdx.x * 64;
    const int oh = blockIdx.y;

#pragma unroll
    for (int i = 0; i < 6; i++) {
        const int idx = i * 256 + tid;
        const int row = idx / 24;
        const int ch  = idx % 24;
        cp16(sAh + row * 400 + ch * 16, pHi + (size_t)(r0 + row) * PK + ch * 8);
        cp16(sAl + row * 400 + ch * 16, pLo + (size_t)(r0 + row) * PK + ch * 8);
        cp16(sBh + row * 400 + ch * 16, wHi + (size_t)(oh * 64 + row) * PK + ch * 8);
        cp16(sBl + row * 400 + ch * 16, wLo + (size_t)(oh * 64 + row) * PK + ch * 8);
    }
    CP_COMMIT();
    CP_WAIT(0);
    __syncthreads();

    const int lane = tid & 31;
    const int wid  = tid >> 5;
    const int mw   = wid & 3;
    const int ow   = wid >> 2;
    const int rsub = lane >> 2;
    const int q    = lane & 3;

    float acc[4][4];
#pragma unroll
    for (int i = 0; i < 4; i++)
#pragma unroll
        for (int j = 0; j < 4; j++) acc[i][j] = 0.0f;

#pragma unroll
    for (int ki = 0; ki < 12; ki++) {
        const int kb2 = ki * 8;
        const uint32_t* Ar = Ah + (mw * 16 + rsub) * PJ_STRIDE + kb2 + q;
        const uint32_t* Alr = Al + (mw * 16 + rsub) * PJ_STRIDE + kb2 + q;
        const uint32_t ah0 = Ar[0],  ah1 = Ar[8 * PJ_STRIDE],  ah2 = Ar[4],  ah3 = Ar[8 * PJ_STRIDE + 4];
        const uint32_t al0 = Alr[0], al1 = Alr[8 * PJ_STRIDE], al2 = Alr[4], al3 = Alr[8 * PJ_STRIDE + 4];

#pragma unroll
        for (int nb = 0; nb < 4; nb++) {
            const int ob = ow * 32 + nb * 8 + rsub;
            const uint32_t* Br = Bh + ob * PJ_STRIDE + kb2 + q;
            const uint32_t* Blr = Bl + ob * PJ_STRIDE + kb2 + q;
            const uint32_t bh0 = Br[0], bh1 = Br[4];
            const uint32_t bl0 = Blr[0], bl1 = Blr[4];

            mma16816(acc[nb], ah0, ah1, ah2, ah3, bh0, bh1);
            mma16816(acc[nb], ah0, ah1, ah2, ah3, bl0, bl1);
            mma16816(acc[nb], al0, al1, al2, al3, bh0, bh1);
        }
    }

    const int row = r0 + mw * 16 + rsub;
#pragma unroll
    for (int nb = 0; nb < 4; nb++) {
        const int col = oh * 64 + ow * 32 + nb * 8 + q * 2;
        *(float2*)(out + (size_t)row * OO + col)       = make_float2(acc[nb][0], acc[nb][1]);
        *(float2*)(out + (size_t)(row + 8) * OO + col) = make_float2(acc[nb][2], acc[nb][3]);
    }
}

// ---------------------------------------------------------------------------
// Launcher
// ---------------------------------------------------------------------------
extern "C" void kernel_launch(void* const* d_in, const int* in_sizes, int n_in,
                              void* d_out, int out_size)
{
    const float* x = nullptr;
    const float* Lm = nullptr;
    const float* W = nullptr;
    const float* theta = nullptr;
    for (int i = 0; i < n_in; i++) {
        switch (in_sizes[i]) {
            case BB * NN * FF: x = (const float*)d_in[i]; break;
            case BB * NN * NN: Lm = (const float*)d_in[i]; break;
            case KK * FF * OO: W = (const float*)d_in[i]; break;
            case KK:           theta = (const float*)d_in[i]; break;
            default: break;
        }
    }
    float* out = (float*)d_out;

    float *bufA = nullptr, *bufB = nullptr;
    __nv_bfloat16 *btgHi = nullptr, *btgLo = nullptr;
    __nv_bfloat16 *btpHi = nullptr, *btpLo = nullptr;
    __nv_bfloat16 *wtHi = nullptr, *wtLo = nullptr;
    cudaGetSymbolAddress((void**)&bufA, g_bufA);
    cudaGetSymbolAddress((void**)&bufB, g_bufB);
    cudaGetSymbolAddress((void**)&btgHi, g_btg_hi);
    cudaGetSymbolAddress((void**)&btgLo, g_btg_lo);
    cudaGetSymbolAddress((void**)&btpHi, g_btp_hi);
    cudaGetSymbolAddress((void**)&btpLo, g_btp_lo);
    cudaGetSymbolAddress((void**)&wtHi, g_wt_hi);
    cudaGetSymbolAddress((void**)&wtLo, g_wt_lo);

    __nv_bfloat16* gHi[2] = { btgHi, btgHi + (size_t)BB * FF * NN };
    __nv_bfloat16* gLo[2] = { btgLo, btgLo + (size_t)BB * FF * NN };

    cudaFuncSetAttribute(cheb_gemm_tc, cudaFuncAttributeMaxDynamicSharedMemorySize, SMEM_TOTAL);
    cudaFuncSetAttribute(proj_mma, cudaFuncAttributeMaxDynamicSharedMemorySize, PJ_SMEM);

    const dim3 gGrid(NN / BM, BB);          // (128, 4) = 512 CTAs
    const dim3 bGrid((BB * FF * NN) / 256);
    const dim3 wGrid((PK * OO) / 256);
    const dim3 pjGrid((BB * NN) / 64, 2);

    prep_w<<<wGrid, 256>>>(W, theta, wtHi, wtLo);
    prep_b<<<bGrid, 256>>>(x, gHi[0], gLo[0], btpHi, btpLo);

    // T1 = L @ x
    cheb_gemm_tc<<<gGrid, GT, SMEM_TOTAL>>>(Lm, gHi[0], gLo[0], x, bufA, 1.0f, 0.0f,
                                            gHi[1], gLo[1], btpHi, btpLo, 1);
    // T2 = 2 L @ T1 - x
    cheb_gemm_tc<<<gGrid, GT, SMEM_TOTAL>>>(Lm, gHi[1], gLo[1], x, bufB, 2.0f, -1.0f,
                                            gHi[0], gLo[0], btpHi, btpLo, 2);
    // T3 = 2 L @ T2 - T1
    cheb_gemm_tc<<<gGrid, GT, SMEM_TOTAL>>>(Lm, gHi[0], gLo[0], bufA, bufA, 2.0f, -1.0f,
                                            gHi[1], gLo[1], btpHi, btpLo, 3);
    // T4 = 2 L @ T3 - T2
    cheb_gemm_tc<<<gGrid, GT, SMEM_TOTAL>>>(Lm, gHi[1], gLo[1], bufB, bufB, 2.0f, -1.0f,
                                            gHi[0], gLo[0], btpHi, btpLo, 4);
    // T5 = 2 L @ T4 - T3
    cheb_gemm_tc<<<gGrid, GT, SMEM_TOTAL>>>(Lm, gHi[0], gLo[0], bufA, bufA, 2.0f, -1.0f,
                                            gHi[1], gLo[1], btpHi, btpLo, 5);

    // out = sum_k theta_k T_k W_k
    proj_mma<<<pjGrid, 256, PJ_SMEM>>>(btpHi, btpLo, wtHi, wtLo, out);
}